// round 5
// baseline (speedup 1.0000x reference)
#include <cuda_runtime.h>
#include <math.h>

#define KN 1024       // N_EMBED (atoms)
#define DD 128        // DIM
#define NN 16384      // number of patches (16*32*32)
#define HW 1024       // 32*32
#define NB 16         // batch

// output flat offsets (tuple flatten order of the reference return)
#define OFF_QD1    2097152
#define OFF_QD2    2097153
#define OFF_IDS    2097154
#define OFF_NSTEPS 18874370
#define OFF_MEAND  18874371
#define OFF_MEANZ  18874372
#define OFF_NORMZ  18874373
#define OFF_TOPP   18874374
#define OFF_NZEROS 18874375

// ---------------- device scratch (allocation-free rule: __device__ globals) ----------
// __align__(16): these are accessed via float4; the language only guarantees 4B
// alignment for float arrays, and misaligned LDG.128 is a hardware trap (err715).
__device__ __align__(16) float d_Dt[KN * DD];    // normalized dictionary, transposed: Dt[k][c]
__device__ __align__(16) float d_G[KN * KN];     // Gram = Dt Dt^T
__device__ __align__(16) float d_DtX[KN * NN];
__device__ __align__(16) float d_Z[KN * NN];     // z_prev / z
__device__ __align__(16) float d_Y0[KN * NN];
__device__ __align__(16) float d_Y1[KN * NN];
__device__ float d_v[KN];
__device__ float d_w[KN];
__device__ float d_scal[4];              // [0]=step, [1]=thr
__device__ float d_meanD_part[KN];
__device__ float d_sumabs_part[2048];
__device__ float d_qd_part[128];
__device__ int   d_hist[16];

// ---------------- tiny init ----------------
__global__ void k_init() {
    if (threadIdx.x < 16) d_hist[threadIdx.x] = 0;
}

// ---------------- normalize dictionary columns; build Dt; per-column |.| sums -------
__global__ void k_normalize(const float* __restrict__ D) {
    int k = blockIdx.x;        // column (atom)
    int c = threadIdx.x;       // 128 threads = row
    float v = D[c * KN + k];
    __shared__ float red[128];
    __shared__ float nrm;
    red[c] = v * v;
    __syncthreads();
    for (int s = 64; s; s >>= 1) { if (c < s) red[c] += red[c + s]; __syncthreads(); }
    if (c == 0) nrm = sqrtf(red[0]);
    __syncthreads();
    float o = v / nrm;
    d_Dt[k * DD + c] = o;
    red[c] = fabsf(o);
    __syncthreads();
    for (int s = 64; s; s >>= 1) { if (c < s) red[c] += red[c + s]; __syncthreads(); }
    if (c == 0) d_meanD_part[k] = red[0];
}

// ---------------- Gram matrix G = Dt * Dt^T (1024x1024, K=128) ----------------------
__global__ __launch_bounds__(256) void k_gram() {
    __shared__ float Ai[32][128];
    __shared__ float Aj[32][128];
    int i0 = blockIdx.y * 32, j0 = blockIdx.x * 32;
    int tid = threadIdx.x;
    #pragma unroll
    for (int l = 0; l < 4; l++) {
        int id = tid + l * 256;
        int r = id >> 5, c4 = id & 31;
        *(float4*)&Ai[r][c4 * 4] = *(const float4*)&d_Dt[(i0 + r) * DD + c4 * 4];
        *(float4*)&Aj[r][c4 * 4] = *(const float4*)&d_Dt[(j0 + r) * DD + c4 * 4];
    }
    __syncthreads();
    int tx = tid & 15, ty = tid >> 4;
    float a00 = 0.f, a01 = 0.f, a10 = 0.f, a11 = 0.f;
    #pragma unroll 4
    for (int c = 0; c < 128; c++) {
        float x0 = Ai[ty * 2 + 0][c], x1 = Ai[ty * 2 + 1][c];
        float y0 = Aj[tx * 2 + 0][c], y1 = Aj[tx * 2 + 1][c];
        a00 += x0 * y0; a01 += x0 * y1; a10 += x1 * y0; a11 += x1 * y1;
    }
    d_G[(i0 + ty * 2 + 0) * KN + j0 + tx * 2 + 0] = a00;
    d_G[(i0 + ty * 2 + 0) * KN + j0 + tx * 2 + 1] = a01;
    d_G[(i0 + ty * 2 + 1) * KN + j0 + tx * 2 + 0] = a10;
    d_G[(i0 + ty * 2 + 1) * KN + j0 + tx * 2 + 1] = a11;
}

// ---------------- power iteration pieces ----------------
__global__ void k_pitinit() {
    for (int i = threadIdx.x; i < KN; i += blockDim.x) d_v[i] = 0.03125f; // 1/sqrt(1024)
}

__global__ void k_matvec() {   // w = G @ v ; one block per row
    int row = blockIdx.x;
    int t = threadIdx.x;       // 128 threads
    const float* g = &d_G[row * KN];
    float s = 0.f;
    for (int j = t; j < KN; j += 128) s += g[j] * d_v[j];
    __shared__ float red[128];
    red[t] = s; __syncthreads();
    for (int k2 = 64; k2; k2 >>= 1) { if (t < k2) red[t] += red[t + k2]; __syncthreads(); }
    if (t == 0) d_w[row] = red[0];
}

__global__ void k_pitnorm() {  // v = w / (||w|| + 1e-12)
    int t = threadIdx.x;       // 256
    float s = 0.f;
    for (int i = t; i < KN; i += 256) { float w = d_w[i]; s += w * w; }
    __shared__ float red[256];
    __shared__ float nrm;
    red[t] = s; __syncthreads();
    for (int k2 = 128; k2; k2 >>= 1) { if (t < k2) red[t] += red[t + k2]; __syncthreads(); }
    if (t == 0) nrm = sqrtf(red[0]) + 1e-12f;
    __syncthreads();
    for (int i = t; i < KN; i += 256) d_v[i] = d_w[i] / nrm;
}

__global__ void k_pitfinal() { // L = v . w ; step = 1/L ; thr = alpha*step
    int t = threadIdx.x;       // 256
    float s = 0.f;
    for (int i = t; i < KN; i += 256) s += d_v[i] * d_w[i];
    __shared__ float red[256];
    red[t] = s; __syncthreads();
    for (int k2 = 128; k2; k2 >>= 1) { if (t < k2) red[t] += red[t + k2]; __syncthreads(); }
    if (t == 0) {
        float step = 1.0f / red[0];
        d_scal[0] = step;
        d_scal[1] = 0.1f * step;
    }
}

// ---------------- DtX = Dt (1024x128) @ X (128x16384) ------------------------------
__global__ __launch_bounds__(256) void k_dtx(const float* __restrict__ X) {
    __shared__ float As[16][128];
    __shared__ float Bs[16][128];
    int tid = threadIdx.x;
    int k0 = blockIdx.x * 128;
    int n0 = blockIdx.y * 128;
    int b = n0 >> 10, hw0 = n0 & 1023;
    const float* Xb = X + b * (DD * HW) + hw0;
    int tx = tid & 15, ty = tid >> 4;
    float acc[8][8];
    #pragma unroll
    for (int i = 0; i < 8; i++)
        #pragma unroll
        for (int j = 0; j < 8; j++) acc[i][j] = 0.f;

    for (int c0 = 0; c0 < DD; c0 += 16) {
        #pragma unroll
        for (int l = 0; l < 2; l++) {
            int id = tid + l * 256;
            int r = id >> 2, q = id & 3;
            float4 av = *(const float4*)&d_Dt[(k0 + r) * DD + c0 + q * 4];
            As[q * 4 + 0][r] = av.x; As[q * 4 + 1][r] = av.y;
            As[q * 4 + 2][r] = av.z; As[q * 4 + 3][r] = av.w;
            int br = id >> 5, bc = id & 31;
            float4 bv = *(const float4*)&Xb[(c0 + br) * HW + bc * 4];
            *(float4*)&Bs[br][bc * 4] = bv;
        }
        __syncthreads();
        #pragma unroll
        for (int kk = 0; kk < 16; kk++) {
            float a[8], bb[8];
            #pragma unroll
            for (int i = 0; i < 8; i++) a[i] = As[kk][ty * 8 + i];
            #pragma unroll
            for (int j = 0; j < 8; j++) bb[j] = Bs[kk][tx * 8 + j];
            #pragma unroll
            for (int i = 0; i < 8; i++)
                #pragma unroll
                for (int j = 0; j < 8; j++) acc[i][j] += a[i] * bb[j];
        }
        __syncthreads();
    }
    #pragma unroll
    for (int i = 0; i < 8; i++) {
        int k = k0 + ty * 8 + i;
        #pragma unroll
        for (int j = 0; j < 8; j++) {
            int n = n0 + tx * 8 + j;
            d_DtX[k * NN + n] = acc[i][j];
        }
    }
}

// ---------------- FISTA iteration 1 (y0 = 0) ----------------
__global__ void k_first() {
    float step = d_scal[0], thr = d_scal[1];
    for (int i = blockIdx.x * blockDim.x + threadIdx.x; i < KN * NN; i += gridDim.x * blockDim.x) {
        float v = step * d_DtX[i];
        float a = fabsf(v) - thr;
        float z = (a > 0.f) ? copysignf(a, v) : 0.f;
        d_Z[i] = z;
        d_Y0[i] = z;   // momentum for iter 1 is 0 -> y1 = z1
    }
}

// ---------------- main FISTA GEMM (W = G @ Y) with fused prox + momentum epilogue ---
__global__ __launch_bounds__(256) void k_fista(float m, int ping) {
    const float* __restrict__ Yin = ping ? d_Y1 : d_Y0;
    float* __restrict__ Yout      = ping ? d_Y0 : d_Y1;
    __shared__ float As[16][128];
    __shared__ float Bs[16][128];
    int tid = threadIdx.x;
    int k0 = blockIdx.x * 128;   // x = k-tile (8) so consecutive CTAs share the Y n-tile
    int n0 = blockIdx.y * 128;
    int tx = tid & 15, ty = tid >> 4;
    float acc[8][8];
    #pragma unroll
    for (int i = 0; i < 8; i++)
        #pragma unroll
        for (int j = 0; j < 8; j++) acc[i][j] = 0.f;

    for (int j0 = 0; j0 < KN; j0 += 16) {
        #pragma unroll
        for (int l = 0; l < 2; l++) {
            int id = tid + l * 256;
            int r = id >> 2, q = id & 3;
            float4 av = *(const float4*)&d_G[(k0 + r) * KN + j0 + q * 4];
            As[q * 4 + 0][r] = av.x; As[q * 4 + 1][r] = av.y;
            As[q * 4 + 2][r] = av.z; As[q * 4 + 3][r] = av.w;
            int br = id >> 5, bc = id & 31;
            float4 bv = *(const float4*)&Yin[(j0 + br) * NN + n0 + bc * 4];
            *(float4*)&Bs[br][bc * 4] = bv;
        }
        __syncthreads();
        #pragma unroll
        for (int kk = 0; kk < 16; kk++) {
            float a[8], bb[8];
            #pragma unroll
            for (int i = 0; i < 8; i++) a[i] = As[kk][ty * 8 + i];
            #pragma unroll
            for (int j = 0; j < 8; j++) bb[j] = Bs[kk][tx * 8 + j];
            #pragma unroll
            for (int i = 0; i < 8; i++)
                #pragma unroll
                for (int j = 0; j < 8; j++) acc[i][j] += a[i] * bb[j];
        }
        __syncthreads();
    }
    float step = d_scal[0], thr = d_scal[1];
    #pragma unroll
    for (int i = 0; i < 8; i++) {
        int k = k0 + ty * 8 + i;
        #pragma unroll
        for (int j = 0; j < 8; j++) {
            int n = n0 + tx * 8 + j;
            int idx = k * NN + n;
            float yv = Yin[idx];
            float dx = d_DtX[idx];
            float zp = d_Z[idx];
            float v = yv - step * (acc[i][j] - dx);
            float a = fabsf(v) - thr;
            float zn = (a > 0.f) ? copysignf(a, v) : 0.f;
            d_Z[idx] = zn;
            Yout[idx] = zn + m * (zn - zp);
        }
    }
}

// ---------------- top-10 per column + 8-bit quantization + stats --------------------
__global__ __launch_bounds__(256) void k_topk() {
    __shared__ float sm[8 * 1025];   // 8 columns, padded to kill bank conflicts
    __shared__ float wsum[8];
    int n0 = blockIdx.x * 8;
    int tid = threadIdx.x;
    for (int idx = tid; idx < 8 * 1024; idx += 256) {
        int k = idx >> 3, c = idx & 7;
        sm[c * 1025 + k] = d_Z[k * NN + n0 + c];
    }
    __syncthreads();
    int warp = tid >> 5, lane = tid & 31;
    float* col = &sm[warp * 1025];
    unsigned mask = 0;
    for (int r = 0; r < 10; r++) {
        float best = -1.0f; int bk = 1 << 30;
        #pragma unroll
        for (int i = 0; i < 32; i++) {
            if (!((mask >> i) & 1u)) {
                float v = fabsf(col[i * 32 + lane]);   // k = i*32 + lane
                if (v > best) { best = v; bk = i * 32 + lane; }
            }
        }
        #pragma unroll
        for (int off = 16; off; off >>= 1) {
            float ov = __shfl_xor_sync(0xffffffffu, best, off);
            int ok = __shfl_xor_sync(0xffffffffu, bk, off);
            if (ov > best || (ov == best && ok < bk)) { best = ov; bk = ok; }
        }
        if (lane == (bk & 31)) mask |= 1u << (bk >> 5);
    }
    float sa = 0.f; int nz = 0;
    #pragma unroll
    for (int i = 0; i < 32; i++) {
        float z = col[i * 32 + lane];
        float q = 0.f;
        if ((mask >> i) & 1u) {
            float zc = fminf(fmaxf(z, -0.55f), 0.55f);
            float u = (zc - (-0.55f)) / (0.55f - (-0.55f));
            u = rintf(u * 256.0f) * 0.00390625f;       // round-half-even, /2^8 exact
            q = u * (0.55f - (-0.55f)) + (-0.55f);
        }
        col[i * 32 + lane] = q;
        sa += fabsf(q);
        nz += (q != 0.f) ? 1 : 0;
    }
    #pragma unroll
    for (int off = 16; off; off >>= 1) {
        sa += __shfl_xor_sync(0xffffffffu, sa, off);
        nz += __shfl_xor_sync(0xffffffffu, nz, off);
    }
    if (lane == 0) { atomicAdd(&d_hist[nz], 1); wsum[warp] = sa; }
    __syncthreads();
    if (tid == 0) {
        float s = 0.f;
        for (int w = 0; w < 8; w++) s += wsum[w];
        d_sumabs_part[blockIdx.x] = s;
    }
    for (int idx = tid; idx < 8 * 1024; idx += 256) {
        int k = idx >> 3, c = idx & 7;
        d_Z[k * NN + n0 + c] = sm[c * 1025 + k];
    }
}

// ---------------- ids output: (b,k) transpose copy of 1024-float rows ---------------
// NOTE: out + OFF_IDS is only 8-byte aligned (OFF_IDS = 2097154 ≡ 2 mod 4 floats),
// so float2 is the widest legal vector here. float4 traps (misaligned address).
__global__ void k_ids(float* __restrict__ out) {
    int bk = blockIdx.x;
    int k = bk & 1023, b = bk >> 10;
    const float2* src = (const float2*)&d_Z[k * NN + b * HW];
    float2* dst = (float2*)(out + OFF_IDS + (size_t)b * (KN * HW) + (size_t)k * HW);
    int t = threadIdx.x;   // 256 threads x 2 float2 = 1024 floats
    dst[t] = src[t];
    dst[t + 256] = src[t + 256];
}

// ---------------- reconstruction R = Dn @ Zq (128 x 16384) + straight-through + qd --
__global__ __launch_bounds__(256) void k_recon(const float* __restrict__ X, float* __restrict__ out) {
    __shared__ float As[16][128];
    __shared__ float Bs[16][128];
    int tid = threadIdx.x;
    int n0 = blockIdx.x * 128;
    int tx = tid & 15, ty = tid >> 4;
    float acc[8][8];
    #pragma unroll
    for (int i = 0; i < 8; i++)
        #pragma unroll
        for (int j = 0; j < 8; j++) acc[i][j] = 0.f;

    for (int k0 = 0; k0 < KN; k0 += 16) {
        #pragma unroll
        for (int l = 0; l < 2; l++) {
            int id = tid + l * 256;
            int r = id >> 5, c4 = id & 31;
            *(float4*)&As[r][c4 * 4] = *(const float4*)&d_Dt[(k0 + r) * DD + c4 * 4];
            *(float4*)&Bs[r][c4 * 4] = *(const float4*)&d_Z[(k0 + r) * NN + n0 + c4 * 4];
        }
        __syncthreads();
        #pragma unroll
        for (int kk = 0; kk < 16; kk++) {
            float a[8], bb[8];
            #pragma unroll
            for (int i = 0; i < 8; i++) a[i] = As[kk][ty * 8 + i];   // c index
            #pragma unroll
            for (int j = 0; j < 8; j++) bb[j] = Bs[kk][tx * 8 + j];  // n index
            #pragma unroll
            for (int i = 0; i < 8; i++)
                #pragma unroll
                for (int j = 0; j < 8; j++) acc[i][j] += a[i] * bb[j];
        }
        __syncthreads();
    }
    int b = n0 >> 10, hw0 = n0 & 1023;
    float sq = 0.f;
    #pragma unroll
    for (int i = 0; i < 8; i++) {
        int c = ty * 8 + i;
        #pragma unroll
        for (int j = 0; j < 8; j++) {
            int hw = hw0 + tx * 8 + j;
            int gi = b * (DD * HW) + c * HW + hw;
            float x = X[gi];
            float d = acc[i][j] - x;
            sq += d * d;
            out[gi] = x + d;   // straight-through: perm + (quantize - perm), op-exact
        }
    }
    __shared__ float red[256];
    red[tid] = sq; __syncthreads();
    for (int k2 = 128; k2; k2 >>= 1) { if (tid < k2) red[tid] += red[tid + k2]; __syncthreads(); }
    if (tid == 0) d_qd_part[blockIdx.x] = red[0];
}

// ---------------- final scalars (deterministic fixed-order reductions) --------------
__global__ void k_scalars(float* __restrict__ out) {
    __shared__ float red[256];
    int t = threadIdx.x;
    // qd
    float s = (t < 128) ? d_qd_part[t] : 0.f;
    red[t] = s; __syncthreads();
    for (int k2 = 128; k2; k2 >>= 1) { if (t < k2) red[t] += red[t + k2]; __syncthreads(); }
    if (t == 0) { float qd = red[0] / 2097152.0f; out[OFF_QD1] = qd; out[OFF_QD2] = qd; }
    __syncthreads();
    // mean|D|
    s = 0.f;
    for (int i = t; i < KN; i += 256) s += d_meanD_part[i];
    red[t] = s; __syncthreads();
    for (int k2 = 128; k2; k2 >>= 1) { if (t < k2) red[t] += red[t + k2]; __syncthreads(); }
    if (t == 0) out[OFF_MEAND] = red[0] / 131072.0f;
    __syncthreads();
    // mean|Z|
    s = 0.f;
    for (int i = t; i < 2048; i += 256) s += d_sumabs_part[i];
    red[t] = s; __syncthreads();
    for (int k2 = 128; k2; k2 >>= 1) { if (t < k2) red[t] += red[t + k2]; __syncthreads(); }
    if (t == 0) out[OFF_MEANZ] = red[0] / 16777216.0f;
    if (t == 0) {
        out[OFF_NSTEPS] = 50.0f;
        int cum = 0, perc = 0, found = 0;
        for (int v = 10; v >= 0; v--) {
            cum += d_hist[v];
            if (!found && cum >= 163) { perc = v; found = 1; }  // 163rd largest norm0
        }
        float sv = 0.f;
        for (int v = 1; v <= 10; v++) sv += (float)v * (float)d_hist[v];
        out[OFF_NORMZ]  = sv / 16384.0f;
        out[OFF_TOPP]   = (float)perc;
        out[OFF_NZEROS] = (float)d_hist[0];
    }
}

// ---------------- host driver ----------------
extern "C" void kernel_launch(void* const* d_in, const int* in_sizes, int n_in,
                              void* d_out, int out_size) {
    (void)n_in; (void)out_size;
    const float* a0 = (const float*)d_in[0];
    const float* a1 = (const float*)d_in[1];
    const float* X; const float* Ddict;
    if (in_sizes[0] == KN * DD) { Ddict = a0; X = a1; }   // robust to input ordering
    else                        { X = a0;     Ddict = a1; }
    float* out = (float*)d_out;

    k_init<<<1, 32>>>();
    k_normalize<<<KN, 128>>>(Ddict);
    k_gram<<<dim3(32, 32), 256>>>();
    k_pitinit<<<1, 256>>>();
    for (int i = 0; i < 20; i++) {
        k_matvec<<<KN, 128>>>();
        k_pitnorm<<<1, 256>>>();
    }
    k_matvec<<<KN, 128>>>();
    k_pitfinal<<<1, 256>>>();

    k_dtx<<<dim3(8, 128), 256>>>(X);
    k_first<<<4096, 256>>>();

    // fp32 scalar recurrence for Nesterov t/momentum, mirroring the JAX op order
    float t = 1.0f;
    {   // iteration 1 (consumed by k_first, momentum 0)
        float tn = (1.0f + sqrtf(1.0f + 4.0f * t * t)) / 2.0f;
        t = tn;
    }
    for (int it = 2; it <= 50; ++it) {
        float tn = (1.0f + sqrtf(1.0f + 4.0f * t * t)) / 2.0f;
        float m = (t - 1.0f) / tn;
        t = tn;
        k_fista<<<dim3(8, 128), 256>>>(m, it & 1);
    }

    k_topk<<<2048, 256>>>();
    k_ids<<<16384, 256>>>(out);
    k_recon<<<128, 256>>>(X, out);
    k_scalars<<<1, 256>>>(out);
}